// round 7
// baseline (speedup 1.0000x reference)
#include <cuda_runtime.h>
#include <cstdint>

#define Bsz   65536
#define Dsz   1024
#define Hsz   8

#define ROWS_PER_CTA 128
#define NTHREADS     128
#define KC           64
#define NSTAGES      16
#define RS           68          // smem x-row stride (floats): 272B, 16B aligned, conflict-free

// smem layout (bytes)
#define MBAR_OFF   0
#define WH_OFF     64
#define BZ_OFF     1088
#define ZW_OFF     1216
#define WD1_OFF    1344
#define BD1_OFF    1504
#define WD2_OFF    1536
#define BD2_OFF    1664
#define WD3_OFF    1696
#define BD3_OFF    1720
#define M1_OFF     1728
#define M2_OFF     1760
#define HDR_BYTES  4096
#define XS_OFF     HDR_BYTES
#define XS_SZ      (ROWS_PER_CTA * RS * 4)            // 34816
#define SMEM_TOTAL (XS_OFF + 2 * XS_SZ)               // 73728  -> 3 CTAs/SM
#define SG_OFF     XS_OFF
#define STAGE_BYTES (ROWS_PER_CTA * KC * 4)           // 32768

// pre-packed mask-folded x-weights: [kp(512)][jj(4)][g(4)] float4 =
// (w[2kp][n0], w[2kp+1][n0], w[2kp][n0+1], w[2kp+1][n0+1]), n0 = jj*2 within gate g
__device__ float4 g_Wk2[512 * 16];

#define FMA2(d, a, b) asm("fma.rn.f32x2 %0, %1, %2, %0;" : "+l"(d) : "l"(a), "l"(b))
#define UNPK(lo, hi, v) asm("mov.b64 {%0, %1}, %2;" : "=f"(lo), "=f"(hi) : "l"(v))

__device__ __forceinline__ void mbar_init(uint32_t a, uint32_t cnt) {
    asm volatile("mbarrier.init.shared.b64 [%0], %1;" :: "r"(a), "r"(cnt) : "memory");
}
__device__ __forceinline__ void mbar_expect_tx(uint32_t a, uint32_t bytes) {
    asm volatile("mbarrier.arrive.expect_tx.shared.b64 _, [%0], %1;" :: "r"(a), "r"(bytes) : "memory");
}
__device__ __forceinline__ void mbar_wait(uint32_t a, uint32_t parity) {
    asm volatile(
        "{\n\t.reg .pred P;\n"
        "LW_%=:\n\t"
        "mbarrier.try_wait.parity.acquire.cta.shared::cta.b64 P, [%0], %1, 0x989680;\n\t"
        "@P bra LD_%=;\n\t"
        "bra LW_%=;\n"
        "LD_%=:\n\t}"
        :: "r"(a), "r"(parity) : "memory");
}
__device__ __forceinline__ void bulk_g2s(uint32_t dst, const void* src, uint32_t bytes, uint32_t mbar) {
    asm volatile(
        "cp.async.bulk.shared::cluster.global.mbarrier::complete_tx::bytes [%0], [%1], %2, [%3];"
        :: "r"(dst), "l"(src), "r"(bytes), "r"(mbar) : "memory");
}
__device__ __forceinline__ float hsig(float x) {
    return __saturatef(fmaf(x, 0.16666667f, 0.5f));
}
__device__ __forceinline__ ulonglong2 ldg_u2(const ulonglong2* p) {
    ulonglong2 v;
    asm("ld.global.nc.v2.u64 {%0, %1}, [%2];" : "=l"(v.x), "=l"(v.y) : "l"(p));
    return v;
}

__global__ void prep_kernel(const float* __restrict__ Wxi, const float* __restrict__ Wxf,
                            const float* __restrict__ Wxc, const float* __restrict__ Wxo,
                            const float* __restrict__ mx) {
    int tid = blockIdx.x * blockDim.x + threadIdx.x;
    if (tid >= 512 * 16) return;
    int kp = tid >> 4;
    int jj = (tid >> 2) & 3;
    int g  = tid & 3;
    int n0 = jj * 2;
    const float* W = (g == 0) ? Wxi : (g == 1) ? Wxf : (g == 2) ? Wxc : Wxo;
    int k0 = kp * 2;
    float m0 = mx[g * Dsz + k0];
    float m1 = mx[g * Dsz + k0 + 1];
    float4 v;
    v.x = m0 * W[k0 * Hsz + n0];
    v.y = m1 * W[(k0 + 1) * Hsz + n0];
    v.z = m0 * W[k0 * Hsz + n0 + 1];
    v.w = m1 * W[(k0 + 1) * Hsz + n0 + 1];
    g_Wk2[tid] = v;
}

struct KParams {
    const float *x, *hp, *cp, *zp;
    const float *Whi, *Whf, *Whc, *Who;
    const float *Wzi, *Wzf, *Wzc, *Wzo;
    const float *bi, *bf, *bc, *bo;
    const float *Wd1, *bd1, *Wd2, *bd2, *Wd3, *bd3;
    const float *mz, *m1, *m2;
    float *out;
};

__device__ __forceinline__ void issue_stage(int s, uint32_t smem_u32, const float* x,
                                            int cta_row0, int tid) {
    int buf = s & 1;
    uint32_t mbar = smem_u32 + MBAR_OFF + 8u * buf;
    if (tid == 0) mbar_expect_tx(mbar, STAGE_BYTES);
    {
        uint32_t dst = smem_u32 + XS_OFF + (uint32_t)buf * XS_SZ + (uint32_t)tid * (RS * 4);
        const float* src = x + (size_t)(cta_row0 + tid) * Dsz + (size_t)s * KC;
        bulk_g2s(dst, src, KC * 4, mbar);
    }
}

__global__ void __launch_bounds__(NTHREADS, 3)
lstm_kernel(KParams p) {
    extern __shared__ char smem[];
    const int tid = threadIdx.x;
    const int w   = tid >> 5;
    const int l   = tid & 31;
    const int ng  = l & 3;           // gate owned by this lane
    const int rq  = l >> 2;          // 0..7
    const int r_base = w * 32 + rq;  // rows r_base + 8*r, r=0..3
    const int cta_row0 = blockIdx.x * ROWS_PER_CTA;

    uint32_t smem_u32 = (uint32_t)__cvta_generic_to_shared(smem);

    if (tid == 0) {
        mbar_init(smem_u32 + MBAR_OFF + 0, 1);
        mbar_init(smem_u32 + MBAR_OFF + 8, 1);
    }
    {
        float* sWh = (float*)(smem + WH_OFF);
#pragma unroll
        for (int i = tid; i < 256; i += NTHREADS) {
            int j = i >> 5, n = i & 31, g = n >> 3, nn = n & 7;
            const float* Wh = (g == 0) ? p.Whi : (g == 1) ? p.Whf : (g == 2) ? p.Whc : p.Who;
            sWh[j * 32 + n] = Wh[j * Hsz + nn];
        }
        if (tid < 32) {
            int g = tid >> 3, nn = tid & 7;
            const float* b  = (g == 0) ? p.bi  : (g == 1) ? p.bf  : (g == 2) ? p.bc  : p.bo;
            const float* Wz = (g == 0) ? p.Wzi : (g == 1) ? p.Wzf : (g == 2) ? p.Wzc : p.Wzo;
            ((float*)(smem + BZ_OFF))[tid] = b[nn];
            ((float*)(smem + ZW_OFF))[tid] = p.mz[g] * Wz[nn];
        }
        if (tid >= 32 && tid < 72)  ((float*)(smem + WD1_OFF))[tid - 32] = p.Wd1[tid - 32];
        if (tid >= 72 && tid < 97)  ((float*)(smem + WD2_OFF))[tid - 72] = p.Wd2[tid - 72];
        if (tid >= 97 && tid < 102) {
            int q = tid - 97;
            ((float*)(smem + WD3_OFF))[q] = p.Wd3[q];
            ((float*)(smem + BD1_OFF))[q] = p.bd1[q];
            ((float*)(smem + BD2_OFF))[q] = p.bd2[q];
            ((float*)(smem + M1_OFF))[q]  = p.m1[q];
            ((float*)(smem + M2_OFF))[q]  = p.m2[q];
        }
        if (tid == 102) ((float*)(smem + BD3_OFF))[0] = p.bd3[0];
    }
    __syncthreads();

    issue_stage(0, smem_u32, p.x, cta_row0, tid);
    issue_stage(1, smem_u32, p.x, cta_row0, tid);

    unsigned long long acc0[8], acc1[8], acc2[8], acc3[8];
#pragma unroll
    for (int j = 0; j < 8; j++) { acc0[j] = 0ull; acc1[j] = 0ull; acc2[j] = 0ull; acc3[j] = 0ull; }

    int ph0 = 0, ph1 = 0;

    // per-lane W pointer: element idx = kp_global*16 + jj*4 + ng  (16B elements)
    const ulonglong2* wlane = (const ulonglong2*)g_Wk2 + ng;

    for (int s = 0; s < NSTAGES; s++) {
        int buf = s & 1;
        if (buf == 0) { mbar_wait(smem_u32 + MBAR_OFF + 0, ph0); ph0 ^= 1; }
        else          { mbar_wait(smem_u32 + MBAR_OFF + 8, ph1); ph1 ^= 1; }

        const float* xsb = (const float*)(smem + XS_OFF + buf * XS_SZ);
        const float* x0p = xsb + (r_base +  0) * RS;
        const float* x1p = xsb + (r_base +  8) * RS;
        const float* x2p = xsb + (r_base + 16) * RS;
        const float* x3p = xsb + (r_base + 24) * RS;
        const ulonglong2* wst = wlane + (size_t)s * (KC / 2) * 16;

#pragma unroll 2
        for (int kp2 = 0; kp2 < KC / 4; kp2++) {
            ulonglong2 xr0 = *(const ulonglong2*)(x0p + kp2 * 4);
            ulonglong2 xr1 = *(const ulonglong2*)(x1p + kp2 * 4);
            ulonglong2 xr2 = *(const ulonglong2*)(x2p + kp2 * 4);
            ulonglong2 xr3 = *(const ulonglong2*)(x3p + kp2 * 4);
            const ulonglong2* wk0 = wst + (size_t)(2 * kp2) * 16;
#pragma unroll
            for (int jj = 0; jj < 4; jj++) {
                ulonglong2 wv = ldg_u2(wk0 + jj * 4);
                FMA2(acc0[jj * 2],     xr0.x, wv.x);
                FMA2(acc0[jj * 2 + 1], xr0.x, wv.y);
                FMA2(acc1[jj * 2],     xr1.x, wv.x);
                FMA2(acc1[jj * 2 + 1], xr1.x, wv.y);
                FMA2(acc2[jj * 2],     xr2.x, wv.x);
                FMA2(acc2[jj * 2 + 1], xr2.x, wv.y);
                FMA2(acc3[jj * 2],     xr3.x, wv.x);
                FMA2(acc3[jj * 2 + 1], xr3.x, wv.y);
            }
            const ulonglong2* wk1 = wst + (size_t)(2 * kp2 + 1) * 16;
#pragma unroll
            for (int jj = 0; jj < 4; jj++) {
                ulonglong2 wv = ldg_u2(wk1 + jj * 4);
                FMA2(acc0[jj * 2],     xr0.y, wv.x);
                FMA2(acc0[jj * 2 + 1], xr0.y, wv.y);
                FMA2(acc1[jj * 2],     xr1.y, wv.x);
                FMA2(acc1[jj * 2 + 1], xr1.y, wv.y);
                FMA2(acc2[jj * 2],     xr2.y, wv.x);
                FMA2(acc2[jj * 2 + 1], xr2.y, wv.y);
                FMA2(acc3[jj * 2],     xr3.y, wv.x);
                FMA2(acc3[jj * 2 + 1], xr3.y, wv.y);
            }
        }
        __syncthreads();
        if (s + 2 < NSTAGES) issue_stage(s + 2, smem_u32, p.x, cta_row0, tid);
    }

    // exchange gate pre-activations through smem: sg[row][g*8+j]
    float* sg = (float*)(smem + SG_OFF);
#pragma unroll
    for (int j = 0; j < 8; j++) {
        float lo, hi;
        UNPK(lo, hi, acc0[j]); sg[(r_base +  0) * 33 + ng * 8 + j] = lo + hi;
        UNPK(lo, hi, acc1[j]); sg[(r_base +  8) * 33 + ng * 8 + j] = lo + hi;
        UNPK(lo, hi, acc2[j]); sg[(r_base + 16) * 33 + ng * 8 + j] = lo + hi;
        UNPK(lo, hi, acc3[j]); sg[(r_base + 24) * 33 + ng * 8 + j] = lo + hi;
    }
    __syncthreads();

    {
        const int rg = cta_row0 + tid;
        const float* sWh = (const float*)(smem + WH_OFF);
        const float* sbz = (const float*)(smem + BZ_OFF);
        const float* szw = (const float*)(smem + ZW_OFF);
        const float* sd1 = (const float*)(smem + WD1_OFF);
        const float* sb1 = (const float*)(smem + BD1_OFF);
        const float* sd2 = (const float*)(smem + WD2_OFF);
        const float* sb2 = (const float*)(smem + BD2_OFF);
        const float* sd3 = (const float*)(smem + WD3_OFF);
        const float  b3  = ((const float*)(smem + BD3_OFF))[0];
        const float* sm1 = (const float*)(smem + M1_OFF);
        const float* sm2 = (const float*)(smem + M2_OFF);

        float pre[32];
#pragma unroll
        for (int n = 0; n < 32; n++) pre[n] = sg[tid * 33 + n];

        float zv = p.zp[rg];
        float hv[8];
#pragma unroll
        for (int j = 0; j < 8; j++) hv[j] = p.hp[(size_t)rg * Hsz + j];

#pragma unroll
        for (int n = 0; n < 32; n++) pre[n] = fmaf(zv, szw[n], pre[n] + sbz[n]);
#pragma unroll
        for (int j = 0; j < 8; j++) {
#pragma unroll
            for (int n = 0; n < 32; n++) pre[n] = fmaf(hv[j], sWh[j * 32 + n], pre[n]);
        }

        float htv[8];
        float* out = p.out;
#pragma unroll
        for (int nn = 0; nn < 8; nn++) {
            float cprev = p.cp[(size_t)rg * Hsz + nn];
            float It = hsig(pre[nn]);
            float Ft = hsig(pre[8 + nn]);
            float Cc = tanhf(pre[16 + nn]);
            float Ot = hsig(pre[24 + nn]);
            float cn = fmaf(Ft, cprev, It * Cc);
            htv[nn] = Ot * tanhf(cn);
            out[(size_t)Bsz * 9 + (size_t)rg * Hsz + nn] = cn;       // ct
            out[(size_t)Bsz     + (size_t)rg * Hsz + nn] = htv[nn];  // ht
        }

        float t1[5];
#pragma unroll
        for (int q = 0; q < 5; q++) {
            float a = sb1[q];
#pragma unroll
            for (int nn = 0; nn < 8; nn++) a = fmaf(htv[nn], sd1[nn * 5 + q], a);
            t1[q] = fmaxf(a, 0.0f) * sm1[q];
        }
        float t2[5];
#pragma unroll
        for (int q = 0; q < 5; q++) {
            float a = sb2[q];
#pragma unroll
            for (int u = 0; u < 5; u++) a = fmaf(t1[u], sd2[u * 5 + q], a);
            t2[q] = fmaxf(a, 0.0f) * sm2[q];
        }
        float a3 = b3;
#pragma unroll
        for (int u = 0; u < 5; u++) a3 = fmaf(t2[u], sd3[u], a3);
        out[rg] = zv + fmaxf(a3, 0.0f);                              // zt
    }
}

extern "C" void kernel_launch(void* const* d_in, const int* in_sizes, int n_in,
                              void* d_out, int out_size) {
    KParams p;
    p.x   = (const float*)d_in[0];
    p.hp  = (const float*)d_in[1];
    p.cp  = (const float*)d_in[2];
    p.zp  = (const float*)d_in[3];
    const float* Wxi = (const float*)d_in[4];
    const float* Wxf = (const float*)d_in[5];
    const float* Wxc = (const float*)d_in[6];
    const float* Wxo = (const float*)d_in[7];
    p.Whi = (const float*)d_in[8];
    p.Whf = (const float*)d_in[9];
    p.Whc = (const float*)d_in[10];
    p.Who = (const float*)d_in[11];
    p.Wzi = (const float*)d_in[12];
    p.Wzf = (const float*)d_in[13];
    p.Wzc = (const float*)d_in[14];
    p.Wzo = (const float*)d_in[15];
    p.bi  = (const float*)d_in[16];
    p.bf  = (const float*)d_in[17];
    p.bc  = (const float*)d_in[18];
    p.bo  = (const float*)d_in[19];
    p.Wd1 = (const float*)d_in[20];
    p.bd1 = (const float*)d_in[21];
    p.Wd2 = (const float*)d_in[22];
    p.bd2 = (const float*)d_in[23];
    p.Wd3 = (const float*)d_in[24];
    p.bd3 = (const float*)d_in[25];
    const float* mx = (const float*)d_in[26];
    p.mz  = (const float*)d_in[27];
    p.m1  = (const float*)d_in[28];
    p.m2  = (const float*)d_in[29];
    p.out = (float*)d_out;

    cudaFuncSetAttribute(lstm_kernel, cudaFuncAttributeMaxDynamicSharedMemorySize, SMEM_TOTAL);

    prep_kernel<<<(512 * 16 + 255) / 256, 256>>>(Wxi, Wxf, Wxc, Wxo, mx);
    lstm_kernel<<<Bsz / ROWS_PER_CTA, NTHREADS, SMEM_TOTAL>>>(p);
}

// round 11
// speedup vs baseline: 2.7083x; 2.7083x over previous
#include <cuda_runtime.h>
#include <cstdint>

#define Bsz   65536
#define Dsz   1024
#define Hsz   8

#define ROWS_PER_CTA 128
#define NT           256
#define KC           64
#define NSTAGES      16
#define RS           68
#define SGS          34          // gate-exchange row stride (floats), EVEN -> float2-aligned

// smem layout (bytes)
#define MBAR_OFF   0
#define WH_OFF     64
#define BZ_OFF     1088
#define ZW_OFF     1216
#define WD1_OFF    1344
#define BD1_OFF    1504
#define WD2_OFF    1536
#define BD2_OFF    1664
#define WD3_OFF    1696
#define BD3_OFF    1720
#define M1_OFF     1728
#define M2_OFF     1760
#define XS_OFF     4096
#define XS_SZ      (ROWS_PER_CTA * RS * 4)            // 34816
#define WS_OFF     (XS_OFF + 2 * XS_SZ)               // 73728
#define WS_SZ      8192                               // 4 kt * 4 nt * 32 lanes * 16B
#define SMEM_TOTAL (WS_OFF + 2 * WS_SZ)               // 90112
#define SG_OFF     XS_OFF
#define STAGE_BYTES (ROWS_PER_CTA * KC * 4 + WS_SZ)   // 40960

// pre-packed B fragments: [stage 16][kt 4][nt 4][lane 32] uint4 = (bh0,bh1,bl0,bl1)
__device__ __align__(16) uint4 g_Bp[NSTAGES * 4 * 4 * 32];

__device__ __forceinline__ uint32_t cvtbf2(float hi, float lo) {
    uint32_t r;
    asm("cvt.rn.bf16x2.f32 %0, %1, %2;" : "=r"(r) : "f"(hi), "f"(lo));
    return r;
}
__device__ __forceinline__ float bf_lo(uint32_t u) { return __uint_as_float(u << 16); }
__device__ __forceinline__ float bf_hi(uint32_t u) { return __uint_as_float(u & 0xffff0000u); }

__device__ __forceinline__ void mbar_init(uint32_t a, uint32_t cnt) {
    asm volatile("mbarrier.init.shared.b64 [%0], %1;" :: "r"(a), "r"(cnt) : "memory");
}
__device__ __forceinline__ void mbar_expect_tx(uint32_t a, uint32_t bytes) {
    asm volatile("mbarrier.arrive.expect_tx.shared.b64 _, [%0], %1;" :: "r"(a), "r"(bytes) : "memory");
}
__device__ __forceinline__ void mbar_wait(uint32_t a, uint32_t parity) {
    asm volatile(
        "{\n\t.reg .pred P;\n"
        "LW_%=:\n\t"
        "mbarrier.try_wait.parity.acquire.cta.shared::cta.b64 P, [%0], %1, 0x989680;\n\t"
        "@P bra LD_%=;\n\t"
        "bra LW_%=;\n"
        "LD_%=:\n\t}"
        :: "r"(a), "r"(parity) : "memory");
}
__device__ __forceinline__ void bulk_g2s(uint32_t dst, const void* src, uint32_t bytes, uint32_t mbar) {
    asm volatile(
        "cp.async.bulk.shared::cluster.global.mbarrier::complete_tx::bytes [%0], [%1], %2, [%3];"
        :: "r"(dst), "l"(src), "r"(bytes), "r"(mbar) : "memory");
}
__device__ __forceinline__ float hsig(float x) {
    return __saturatef(fmaf(x, 0.16666667f, 0.5f));
}
__device__ __forceinline__ void mma16816(float* c, uint32_t a0, uint32_t a1, uint32_t a2, uint32_t a3,
                                         uint32_t b0, uint32_t b1) {
    asm volatile(
        "mma.sync.aligned.m16n8k16.row.col.f32.bf16.bf16.f32 "
        "{%0,%1,%2,%3},{%4,%5,%6,%7},{%8,%9},{%0,%1,%2,%3};"
        : "+f"(c[0]), "+f"(c[1]), "+f"(c[2]), "+f"(c[3])
        : "r"(a0), "r"(a1), "r"(a2), "r"(a3), "r"(b0), "r"(b1));
}

// ---------------- prep: fold m_x into W, split bf16 hi/lo, pack mma B fragments ----------------
__global__ void prep_B(const float* __restrict__ Wxi, const float* __restrict__ Wxf,
                       const float* __restrict__ Wxc, const float* __restrict__ Wxo,
                       const float* __restrict__ mx) {
    int i = blockIdx.x * blockDim.x + threadIdx.x;
    if (i >= 64 * 4 * 32) return;
    int lane = i & 31;
    int nt   = (i >> 5) & 3;
    int ktg  = i >> 7;            // global k-tile 0..63
    int g    = lane >> 2;
    int t4   = lane & 3;
    int n    = nt * 8 + g;        // output col 0..31
    int gate = n >> 3, nn = n & 7;
    const float* W = (gate == 0) ? Wxi : (gate == 1) ? Wxf : (gate == 2) ? Wxc : Wxo;
    int kb = ktg * 16 + t4 * 2;
    float w00 = mx[gate * Dsz + kb]     * W[kb * Hsz + nn];
    float w01 = mx[gate * Dsz + kb + 1] * W[(kb + 1) * Hsz + nn];
    float w10 = mx[gate * Dsz + kb + 8] * W[(kb + 8) * Hsz + nn];
    float w11 = mx[gate * Dsz + kb + 9] * W[(kb + 9) * Hsz + nn];
    uint4 v;
    v.x = cvtbf2(w01, w00);                                   // bh0 (k lo pair)
    v.y = cvtbf2(w11, w10);                                   // bh1 (k hi pair)
    v.z = cvtbf2(w01 - bf_hi(v.x), w00 - bf_lo(v.x));         // bl0
    v.w = cvtbf2(w11 - bf_hi(v.y), w10 - bf_lo(v.y));         // bl1
    int stage = ktg >> 2, kt = ktg & 3;
    g_Bp[((stage * 4 + kt) * 4 + nt) * 32 + lane] = v;
}

struct KParams {
    const float *x, *hp, *cp, *zp;
    const float *Whi, *Whf, *Whc, *Who;
    const float *Wzi, *Wzf, *Wzc, *Wzo;
    const float *bi, *bf, *bc, *bo;
    const float *Wd1, *bd1, *Wd2, *bd2, *Wd3, *bd3;
    const float *mz, *m1, *m2;
    float *out;
};

__device__ __forceinline__ void issue_stage(int s, uint32_t smem_u32, const float* x,
                                            int cta_row0, int tid) {
    int buf = s & 1;
    uint32_t mbar = smem_u32 + MBAR_OFF + 8u * buf;
    if (tid == 0) mbar_expect_tx(mbar, STAGE_BYTES);
    if (tid < ROWS_PER_CTA) {
        uint32_t dst = smem_u32 + XS_OFF + (uint32_t)buf * XS_SZ + (uint32_t)tid * (RS * 4);
        const float* src = x + (size_t)(cta_row0 + tid) * Dsz + (size_t)s * KC;
        bulk_g2s(dst, src, KC * 4, mbar);
    } else if (tid == ROWS_PER_CTA) {
        uint32_t dst = smem_u32 + WS_OFF + (uint32_t)buf * WS_SZ;
        const char* src = (const char*)g_Bp + (size_t)s * WS_SZ;
        bulk_g2s(dst, src, WS_SZ, mbar);
    }
}

__global__ void __launch_bounds__(NT, 2)
lstm_kernel(KParams p) {
    extern __shared__ char smem[];
    const int tid = threadIdx.x;
    const int w   = tid >> 5;        // warp = m-tile (16 rows)
    const int lane = tid & 31;
    const int g   = lane >> 2;
    const int t4  = lane & 3;
    const int lr0 = w * 16 + g;      // local row for frag rows g
    const int lr1 = lr0 + 8;
    const int cta_row0 = blockIdx.x * ROWS_PER_CTA;

    uint32_t smem_u32 = (uint32_t)__cvta_generic_to_shared(smem);

    if (tid == 0) {
        mbar_init(smem_u32 + MBAR_OFF + 0, 1);
        mbar_init(smem_u32 + MBAR_OFF + 8, 1);
    }
    {
        float* sWh = (float*)(smem + WH_OFF);
        if (tid < 256) {
            int j = tid >> 5, n = tid & 31, gg = n >> 3, nn = n & 7;
            const float* Wh = (gg == 0) ? p.Whi : (gg == 1) ? p.Whf : (gg == 2) ? p.Whc : p.Who;
            sWh[j * 32 + n] = Wh[j * Hsz + nn];
        }
        if (tid < 32) {
            int gg = tid >> 3, nn = tid & 7;
            const float* b  = (gg == 0) ? p.bi  : (gg == 1) ? p.bf  : (gg == 2) ? p.bc  : p.bo;
            const float* Wz = (gg == 0) ? p.Wzi : (gg == 1) ? p.Wzf : (gg == 2) ? p.Wzc : p.Wzo;
            ((float*)(smem + BZ_OFF))[tid] = b[nn];
            ((float*)(smem + ZW_OFF))[tid] = p.mz[gg] * Wz[nn];
        }
        if (tid >= 32 && tid < 72)  ((float*)(smem + WD1_OFF))[tid - 32] = p.Wd1[tid - 32];
        if (tid >= 72 && tid < 97)  ((float*)(smem + WD2_OFF))[tid - 72] = p.Wd2[tid - 72];
        if (tid >= 97 && tid < 102) {
            int q = tid - 97;
            ((float*)(smem + WD3_OFF))[q] = p.Wd3[q];
            ((float*)(smem + BD1_OFF))[q] = p.bd1[q];
            ((float*)(smem + BD2_OFF))[q] = p.bd2[q];
            ((float*)(smem + M1_OFF))[q]  = p.m1[q];
            ((float*)(smem + M2_OFF))[q]  = p.m2[q];
        }
        if (tid == 102) ((float*)(smem + BD3_OFF))[0] = p.bd3[0];
    }
    __syncthreads();

    issue_stage(0, smem_u32, p.x, cta_row0, tid);
    issue_stage(1, smem_u32, p.x, cta_row0, tid);

    float acc[4][4];
#pragma unroll
    for (int nt = 0; nt < 4; nt++)
#pragma unroll
        for (int q = 0; q < 4; q++) acc[nt][q] = 0.0f;

    int ph0 = 0, ph1 = 0;

    for (int s = 0; s < NSTAGES; s++) {
        int buf = s & 1;
        if (buf == 0) { mbar_wait(smem_u32 + MBAR_OFF + 0, ph0); ph0 ^= 1; }
        else          { mbar_wait(smem_u32 + MBAR_OFF + 8, ph1); ph1 ^= 1; }

        const float* xsb = (const float*)(smem + XS_OFF + buf * XS_SZ);
        const uint4* ws  = (const uint4*)(smem + WS_OFF + buf * WS_SZ);
        const float* xg  = xsb + lr0 * RS + 2 * t4;
        const float* xg8 = xsb + lr1 * RS + 2 * t4;

#pragma unroll
        for (int kt = 0; kt < 4; kt++) {
            float2 xa = *(const float2*)(xg  + kt * 16);
            float2 xb = *(const float2*)(xg  + kt * 16 + 8);
            float2 xc = *(const float2*)(xg8 + kt * 16);
            float2 xd = *(const float2*)(xg8 + kt * 16 + 8);
            // A frag: a0:(g,2t..), a1:(g+8,2t..), a2:(g,2t+8..), a3:(g+8,2t+8..)
            uint32_t ah0 = cvtbf2(xa.y, xa.x);
            uint32_t ah1 = cvtbf2(xc.y, xc.x);
            uint32_t ah2 = cvtbf2(xb.y, xb.x);
            uint32_t ah3 = cvtbf2(xd.y, xd.x);
            uint32_t al0 = cvtbf2(xa.y - bf_hi(ah0), xa.x - bf_lo(ah0));
            uint32_t al1 = cvtbf2(xc.y - bf_hi(ah1), xc.x - bf_lo(ah1));
            uint32_t al2 = cvtbf2(xb.y - bf_hi(ah2), xb.x - bf_lo(ah2));
            uint32_t al3 = cvtbf2(xd.y - bf_hi(ah3), xd.x - bf_lo(ah3));
#pragma unroll
            for (int nt = 0; nt < 4; nt++) {
                uint4 bv = ws[(kt * 4 + nt) * 32 + lane];
                mma16816(acc[nt], ah0, ah1, ah2, ah3, bv.x, bv.y);   // xh @ Wh
                mma16816(acc[nt], al0, al1, al2, al3, bv.x, bv.y);   // xl @ Wh
                mma16816(acc[nt], ah0, ah1, ah2, ah3, bv.z, bv.w);   // xh @ Wl
            }
        }
        __syncthreads();
        if (s + 2 < NSTAGES) issue_stage(s + 2, smem_u32, p.x, cta_row0, tid);
    }

    // exchange pre-activations: sg[row][n]; c0,c1:(row g, col 2t,2t+1), c2,c3:(row g+8, ...)
    float* sg = (float*)(smem + SG_OFF);
#pragma unroll
    for (int nt = 0; nt < 4; nt++) {
        *(float2*)&sg[lr0 * SGS + nt * 8 + 2 * t4] = make_float2(acc[nt][0], acc[nt][1]);
        *(float2*)&sg[lr1 * SGS + nt * 8 + 2 * t4] = make_float2(acc[nt][2], acc[nt][3]);
    }
    __syncthreads();

    if (tid < ROWS_PER_CTA) {
        const int rg = cta_row0 + tid;
        const float* sWh = (const float*)(smem + WH_OFF);
        const float* sbz = (const float*)(smem + BZ_OFF);
        const float* szw = (const float*)(smem + ZW_OFF);
        const float* sd1 = (const float*)(smem + WD1_OFF);
        const float* sb1 = (const float*)(smem + BD1_OFF);
        const float* sd2 = (const float*)(smem + WD2_OFF);
        const float* sb2 = (const float*)(smem + BD2_OFF);
        const float* sd3 = (const float*)(smem + WD3_OFF);
        const float  b3  = ((const float*)(smem + BD3_OFF))[0];
        const float* sm1 = (const float*)(smem + M1_OFF);
        const float* sm2 = (const float*)(smem + M2_OFF);

        float pre[32];
#pragma unroll
        for (int n = 0; n < 32; n++) pre[n] = sg[tid * SGS + n];

        float zv = p.zp[rg];
        float hv[8];
#pragma unroll
        for (int j = 0; j < 8; j++) hv[j] = p.hp[(size_t)rg * Hsz + j];

#pragma unroll
        for (int n = 0; n < 32; n++) pre[n] = fmaf(zv, szw[n], pre[n] + sbz[n]);
#pragma unroll
        for (int j = 0; j < 8; j++) {
#pragma unroll
            for (int n = 0; n < 32; n++) pre[n] = fmaf(hv[j], sWh[j * 32 + n], pre[n]);
        }

        float htv[8];
        float* out = p.out;
#pragma unroll
        for (int nn = 0; nn < 8; nn++) {
            float cprev = p.cp[(size_t)rg * Hsz + nn];
            float It = hsig(pre[nn]);
            float Ft = hsig(pre[8 + nn]);
            float Cc = tanhf(pre[16 + nn]);
            float Ot = hsig(pre[24 + nn]);
            float cn = fmaf(Ft, cprev, It * Cc);
            htv[nn] = Ot * tanhf(cn);
            out[(size_t)Bsz * 9 + (size_t)rg * Hsz + nn] = cn;       // ct
            out[(size_t)Bsz     + (size_t)rg * Hsz + nn] = htv[nn];  // ht
        }

        float t1[5];
#pragma unroll
        for (int q = 0; q < 5; q++) {
            float a = sb1[q];
#pragma unroll
            for (int nn = 0; nn < 8; nn++) a = fmaf(htv[nn], sd1[nn * 5 + q], a);
            t1[q] = fmaxf(a, 0.0f) * sm1[q];
        }
        float t2[5];
#pragma unroll
        for (int q = 0; q < 5; q++) {
            float a = sb2[q];
#pragma unroll
            for (int u = 0; u < 5; u++) a = fmaf(t1[u], sd2[u * 5 + q], a);
            t2[q] = fmaxf(a, 0.0f) * sm2[q];
        }
        float a3 = b3;
#pragma unroll
        for (int u = 0; u < 5; u++) a3 = fmaf(t2[u], sd3[u], a3);
        out[rg] = zv + fmaxf(a3, 0.0f);                              // zt
    }
}

extern "C" void kernel_launch(void* const* d_in, const int* in_sizes, int n_in,
                              void* d_out, int out_size) {
    KParams p;
    p.x   = (const float*)d_in[0];
    p.hp  = (const float*)d_in[1];
    p.cp  = (const float*)d_in[2];
    p.zp  = (const float*)d_in[3];
    const float* Wxi = (const float*)d_in[4];
    const float* Wxf = (const float*)d_in[5];
    const float* Wxc = (const float*)d_in[6];
    const float* Wxo = (const float*)d_in[7];
    p.Whi = (const float*)d_in[8];
    p.Whf = (const float*)d_in[9];
    p.Whc = (const float*)d_in[10];
    p.Who = (const float*)d_in[11];
    p.Wzi = (const float*)d_in[12];
    p.Wzf = (const float*)d_in[13];
    p.Wzc = (const float*)d_in[14];
    p.Wzo = (const float*)d_in[15];
    p.bi  = (const float*)d_in[16];
    p.bf  = (const float*)d_in[17];
    p.bc  = (const float*)d_in[18];
    p.bo  = (const float*)d_in[19];
    p.Wd1 = (const float*)d_in[20];
    p.bd1 = (const float*)d_in[21];
    p.Wd2 = (const float*)d_in[22];
    p.bd2 = (const float*)d_in[23];
    p.Wd3 = (const float*)d_in[24];
    p.bd3 = (const float*)d_in[25];
    const float* mx = (const float*)d_in[26];
    p.mz  = (const float*)d_in[27];
    p.m1  = (const float*)d_in[28];
    p.m2  = (const float*)d_in[29];
    p.out = (float*)d_out;

    cudaFuncSetAttribute(lstm_kernel, cudaFuncAttributeMaxDynamicSharedMemorySize, SMEM_TOTAL);

    prep_B<<<(64 * 4 * 32 + 255) / 256, 256>>>(Wxi, Wxf, Wxc, Wxo, mx);
    lstm_kernel<<<Bsz / ROWS_PER_CTA, NT, SMEM_TOTAL>>>(p);
}